// round 4
// baseline (speedup 1.0000x reference)
#include <cuda_runtime.h>
#include <math.h>

// Problem constants
#define NB 4
#define NC 256
#define IH 224
#define IW 224
#define FF 112
#define FFFF (FF*FF)
#define HWSZ (IH*IW)
#define CHWSZ (NC*HWSZ)
#define SPLIT 2
#define CPS (NC/SPLIT)       // channels per split = 128

// ---------------- Kernel A tiling ----------------
#define ATH 8
#define ATW 16
#define A_THREADS 128
#define A_HR_ROWS 21
#define A_HR_COLS 37
#define A_HR_STRIDE 40
#define A_BL_COLS 33
#define A_BL_STRIDE 36
#define A_BLR_ROWS 17

// ---------------- Kernel B tiling ----------------
#define BTH 16
#define BTW 16
#define B_THREADS 256
#define CG 8
#define B_HR_ROWS 37
#define B_HR_COLS 37
#define B_HR_STRIDE 40
#define B_BL_COLS 33
#define B_BL_STRIDE 36
#define B_BLR_ROWS 33

typedef unsigned long long u64;

// scratch: partial logits (4*2, 9, 112, 112) = 3.6 MB ; attn (4, 9, 112, 112) = 1.8 MB
__device__ float g_part[NB * SPLIT * 9 * FFFF];
__device__ float g_attn[NB * 9 * FFFF];

// ---------------- f32x2 packed helpers ----------------
__device__ __forceinline__ u64 pk(float lo, float hi) {
    u64 d; asm("mov.b64 %0,{%1,%2};" : "=l"(d) : "f"(lo), "f"(hi)); return d;
}
__device__ __forceinline__ void unpk(u64 v, float& lo, float& hi) {
    asm("mov.b64 {%0,%1},%2;" : "=f"(lo), "=f"(hi) : "l"(v));
}
__device__ __forceinline__ u64 f2_add(u64 a, u64 b) {
    u64 d; asm("add.rn.f32x2 %0,%1,%2;" : "=l"(d) : "l"(a), "l"(b)); return d;
}
__device__ __forceinline__ u64 f2_mul(u64 a, u64 b) {
    u64 d; asm("mul.rn.f32x2 %0,%1,%2;" : "=l"(d) : "l"(a), "l"(b)); return d;
}
__device__ __forceinline__ u64 f2_fma(u64 a, u64 b, u64 c) {
    u64 d; asm("fma.rn.f32x2 %0,%1,%2,%3;" : "=l"(d) : "l"(a), "l"(b), "l"(c)); return d;
}

// ---- mask dtype sniffing (JAX bool may arrive as int32 / float32 / uint8) ----
// int32 bools -> first 32 words all in {0,1}; float32 bools -> all in
// {0, 0x3F800000}; uint8 bools (80% ones) -> neither, w.p. 1-1e-67.
__device__ __forceinline__ int detect_mask_mode(const void* m) {
    const unsigned int* w = (const unsigned int*)m;
    bool all01 = true, allf = true;
#pragma unroll
    for (int i = 0; i < 32; i++) {
        unsigned int v = w[i];
        if (v > 1u) all01 = false;
        if (v != 0u && v != 0x3F800000u) allf = false;
    }
    return all01 ? 0 : (allf ? 1 : 2);
}
__device__ __forceinline__ bool mask_val(const void* m, int mode, long idx) {
    if (mode == 0) return ((const int*)m)[idx] != 0;
    if (mode == 1) return ((const float*)m)[idx] != 0.0f;
    return ((const unsigned char*)m)[idx] != 0;
}

// ============================================================
// Kernel A1: blur -> 3x3 stride-2 conv, 9 out ch, partial over 128 channels
// grid (7, 14, NB*SPLIT), block 128 ; 2 channels per iteration (f32x2 packed)
// ============================================================
__global__ __launch_bounds__(A_THREADS)
void attn_A1(const float* __restrict__ hr,
             const float* __restrict__ wk,     // (9,256,3,3)
             float g0, float g1, float g2)
{
    __shared__ __align__(16) u64 s_hr[A_HR_ROWS * A_HR_STRIDE];
    __shared__ __align__(16) u64 s_tmp[A_HR_ROWS * A_BL_STRIDE];
    __shared__ __align__(16) u64 s_blr[A_BLR_ROWS * A_BL_STRIDE];
    __shared__ __align__(16) u64 s_w[9 * 12];   // [tap t][k] packed channel pair

    const int z   = blockIdx.z;
    const int b   = z >> 1;
    const int cbase = (z & 1) * CPS;
    const int tx0 = blockIdx.x * ATW;
    const int ty0 = blockIdx.y * ATH;
    const int tid = threadIdx.x;

    const int R0 = 2 * ty0 - 3;
    const int C0 = 2 * tx0 - 3;

    const u64 g0_2 = pk(g0, g0), g1_2 = pk(g1, g1), g2_2 = pk(g2, g2);

    // hr load slots (channel-invariant): 21*37 = 777
    int goff[7], soff[7];
#pragma unroll
    for (int s = 0; s < 7; s++) {
        int idx = tid + s * A_THREADS;
        if (idx < A_HR_ROWS * A_HR_COLS) {
            int i = idx / A_HR_COLS, j = idx % A_HR_COLS;
            int gr = R0 + i, gc = C0 + j;
            soff[s] = i * A_HR_STRIDE + j;
            goff[s] = (gr >= 0 && gr < IH && gc >= 0 && gc < IW) ? (gr * IW + gc) : -1;
        } else { soff[s] = -1; goff[s] = -1; }
    }
    // hblur slots: 21*33 = 693
    int hb_in[6], hb_out[6]; u64 hb_m[6];
#pragma unroll
    for (int s = 0; s < 6; s++) {
        int idx = tid + s * A_THREADS;
        if (idx < A_HR_ROWS * A_BL_COLS) {
            int i = idx / A_BL_COLS, j = idx % A_BL_COLS;
            hb_in[s]  = i * A_HR_STRIDE + j;
            hb_out[s] = i * A_BL_STRIDE + j;
            float m = ((2 * tx0 - 1 + j) < 0) ? 0.0f : 1.0f;  // unfold left pad = exact 0
            hb_m[s] = pk(m, m);
        } else hb_in[s] = -1;
    }
    // vblur slots: 17*33 = 561
    int vb_in[5], vb_out[5]; u64 vb_m[5];
#pragma unroll
    for (int s = 0; s < 5; s++) {
        int idx = tid + s * A_THREADS;
        if (idx < A_BLR_ROWS * A_BL_COLS) {
            int i = idx / A_BL_COLS, j = idx % A_BL_COLS;
            vb_in[s]  = i * A_BL_STRIDE + j;
            vb_out[s] = i * A_BL_STRIDE + j;
            float m = ((2 * ty0 - 1 + i) < 0) ? 0.0f : 1.0f;  // unfold top pad = exact 0
            vb_m[s] = pk(m, m);
        } else vb_in[s] = -1;
    }

    const int ty = tid / ATW, tx = tid % ATW;

    u64 acc[9];
#pragma unroll
    for (int k = 0; k < 9; k++) acc[k] = 0ull;

    const float* hr_b = hr + (long)b * CHWSZ + (long)cbase * HWSZ;
    const int wk_k = tid / 9, wk_t = tid % 9;

#pragma unroll 1
    for (int ci = 0; ci < CPS / 2; ci++) {
        const float* hp0 = hr_b + (2 * ci) * HWSZ;
        const float* hp1 = hp0 + HWSZ;
#pragma unroll
        for (int s = 0; s < 7; s++) {
            if (soff[s] >= 0) {
                s_hr[soff[s]] = (goff[s] >= 0) ? pk(hp0[goff[s]], hp1[goff[s]]) : 0ull;
            }
        }
        if (tid < 81) {
            int c0 = cbase + 2 * ci;
            s_w[wk_t * 12 + wk_k] = pk(wk[(wk_k * NC + c0) * 9 + wk_t],
                                       wk[(wk_k * NC + c0 + 1) * 9 + wk_t]);
        }
        __syncthreads();

        // horizontal 5-tap blur (packed)
#pragma unroll
        for (int s = 0; s < 6; s++) {
            if (hb_in[s] >= 0) {
                const u64* p = &s_hr[hb_in[s]];
                u64 v = f2_mul(g2_2, f2_add(p[0], p[4]));
                v = f2_fma(g1_2, f2_add(p[1], p[3]), v);
                v = f2_fma(g0_2, p[2], v);
                s_tmp[hb_out[s]] = f2_mul(v, hb_m[s]);
            }
        }
        __syncthreads();

        // vertical 5-tap blur (packed)
#pragma unroll
        for (int s = 0; s < 5; s++) {
            if (vb_in[s] >= 0) {
                const u64* p = &s_tmp[vb_in[s]];
                u64 v = f2_mul(g2_2, f2_add(p[0], p[4 * A_BL_STRIDE]));
                v = f2_fma(g1_2, f2_add(p[A_BL_STRIDE], p[3 * A_BL_STRIDE]), v);
                v = f2_fma(g0_2, p[2 * A_BL_STRIDE], v);
                s_blr[vb_out[s]] = f2_mul(v, vb_m[s]);
            }
        }
        __syncthreads();

        // 3x3 stride-2 conv taps -> 9 output channels, packed 2 input channels.
        // Weight LDS batched ahead of the FMA chain for MLP.
        const u64* brow = &s_blr[(2 * ty) * A_BL_STRIDE + 2 * tx];
#pragma unroll
        for (int kh = 0; kh < 3; kh++) {
#pragma unroll
            for (int kw = 0; kw < 3; kw++) {
                const int t = kh * 3 + kw;
                const ulonglong2* wp = (const ulonglong2*)&s_w[t * 12];
                const u64 v = brow[kh * A_BL_STRIDE + kw];
                const ulonglong2 w01 = wp[0];
                const ulonglong2 w23 = wp[1];
                const ulonglong2 w45 = wp[2];
                const ulonglong2 w67 = wp[3];
                const u64 w8 = s_w[t * 12 + 8];
                acc[0] = f2_fma(v, w01.x, acc[0]);
                acc[1] = f2_fma(v, w01.y, acc[1]);
                acc[2] = f2_fma(v, w23.x, acc[2]);
                acc[3] = f2_fma(v, w23.y, acc[3]);
                acc[4] = f2_fma(v, w45.x, acc[4]);
                acc[5] = f2_fma(v, w45.y, acc[5]);
                acc[6] = f2_fma(v, w67.x, acc[6]);
                acc[7] = f2_fma(v, w67.y, acc[7]);
                acc[8] = f2_fma(v, w8,    acc[8]);
            }
        }
        __syncthreads();
    }

    const int y = ty0 + ty, x = tx0 + tx;
    const long pbase = ((long)z * 9) * FFFF + (long)y * FF + x;
#pragma unroll
    for (int k = 0; k < 9; k++) {
        float lo, hi; unpk(acc[k], lo, hi);
        g_part[pbase + (long)k * FFFF] = lo + hi;
    }
}

// ============================================================
// Kernel A2: combine partials + kbias, mask, lbias, softmax -> g_attn
// grid 784, block 256 (one thread per (b,y,x))
// ============================================================
__global__ __launch_bounds__(256)
void attn_A2(const float* __restrict__ kbias,
             const float* __restrict__ lbias,
             const void*  __restrict__ mask)
{
    const int idx = blockIdx.x * 256 + threadIdx.x;
    if (idx >= NB * FFFF) return;
    const int b = idx / FFFF;
    const int p = idx % FFFF;
    const int mode = detect_mask_mode(mask);

    const long p0 = ((long)(b * 2 + 0) * 9) * FFFF + p;
    const long p1 = ((long)(b * 2 + 1) * 9) * FFFF + p;
    const long mbase = ((long)b * 9) * FFFF + p;

    float lg[9];
    float mx = -1e30f;
#pragma unroll
    for (int k = 0; k < 9; k++) {
        float l = g_part[p0 + (long)k * FFFF] + g_part[p1 + (long)k * FFFF] + kbias[k];
        bool mk = mask_val(mask, mode, mbase + (long)k * FFFF);
        l = (mk ? l : 0.0f) + lbias[k];
        lg[k] = l;
        mx = fmaxf(mx, l);
    }
    float sum = 0.0f;
#pragma unroll
    for (int k = 0; k < 9; k++) { lg[k] = expf(lg[k] - mx); sum += lg[k]; }
    const float inv = 1.0f / sum;
#pragma unroll
    for (int k = 0; k < 9; k++) g_attn[mbase + (long)k * FFFF] = lg[k] * inv;
}

// ============================================================
// Kernel B: out[b,c,y,x] = sum_k blurred[b,c,2y-1+kh,2x-1+kw] * attn[b,k,y,x]
// grid (7, 7, 128), block 256 ; CG=8 channels per CTA, 2 per iteration packed
// ============================================================
__global__ __launch_bounds__(B_THREADS)
void attn_B(const float* __restrict__ hr,
            float* __restrict__ out,
            float g0, float g1, float g2)
{
    __shared__ __align__(16) u64 s_hr[B_HR_ROWS * B_HR_STRIDE];
    __shared__ __align__(16) u64 s_tmp[B_HR_ROWS * B_BL_STRIDE];
    __shared__ __align__(16) u64 s_blr[B_BLR_ROWS * B_BL_STRIDE];

    const int z  = blockIdx.z;
    const int b  = z / (NC / CG);
    const int cg = z % (NC / CG);
    const int tx0 = blockIdx.x * BTW;
    const int ty0 = blockIdx.y * BTH;
    const int tid = threadIdx.x;
    const int ty = tid / BTW, tx = tid % BTW;
    const int y = ty0 + ty, x = tx0 + tx;

    const int R0 = 2 * ty0 - 3;
    const int C0 = 2 * tx0 - 3;

    const u64 g0_2 = pk(g0, g0), g1_2 = pk(g1, g1), g2_2 = pk(g2, g2);

    // attn broadcast-packed: same attn weight applied to both packed channels
    u64 a2[9];
    {
        const long abase = ((long)b * 9) * FFFF + (long)y * FF + x;
#pragma unroll
        for (int k = 0; k < 9; k++) {
            float a = g_attn[abase + (long)k * FFFF];
            a2[k] = pk(a, a);
        }
    }

    int goff[6], soff[6];
#pragma unroll
    for (int s = 0; s < 6; s++) {
        int idx = tid + s * B_THREADS;
        if (idx < B_HR_ROWS * B_HR_COLS) {
            int i = idx / B_HR_COLS, j = idx % B_HR_COLS;
            int gr = R0 + i, gc = C0 + j;
            soff[s] = i * B_HR_STRIDE + j;
            goff[s] = (gr >= 0 && gr < IH && gc >= 0 && gc < IW) ? (gr * IW + gc) : -1;
        } else { soff[s] = -1; goff[s] = -1; }
    }
    int hb_in[5], hb_out[5]; u64 hb_m[5];
#pragma unroll
    for (int s = 0; s < 5; s++) {
        int idx = tid + s * B_THREADS;
        if (idx < B_HR_ROWS * B_BL_COLS) {
            int i = idx / B_BL_COLS, j = idx % B_BL_COLS;
            hb_in[s]  = i * B_HR_STRIDE + j;
            hb_out[s] = i * B_BL_STRIDE + j;
            float m = ((2 * tx0 - 1 + j) < 0) ? 0.0f : 1.0f;
            hb_m[s] = pk(m, m);
        } else hb_in[s] = -1;
    }
    int vb_in[5], vb_out[5]; u64 vb_m[5];
#pragma unroll
    for (int s = 0; s < 5; s++) {
        int idx = tid + s * B_THREADS;
        if (idx < B_BLR_ROWS * B_BL_COLS) {
            int i = idx / B_BL_COLS, j = idx % B_BL_COLS;
            vb_in[s]  = i * B_BL_STRIDE + j;
            vb_out[s] = i * B_BL_STRIDE + j;
            float m = ((2 * ty0 - 1 + i) < 0) ? 0.0f : 1.0f;
            vb_m[s] = pk(m, m);
        } else vb_in[s] = -1;
    }

    const float* hr_b = hr + (long)b * CHWSZ + (long)cg * CG * HWSZ;
    float* out_b = out + ((long)b * NC + (long)cg * CG) * FFFF;

#pragma unroll 1
    for (int pi = 0; pi < CG / 2; pi++) {
        const float* hp0 = hr_b + (2 * pi) * HWSZ;
        const float* hp1 = hp0 + HWSZ;
#pragma unroll
        for (int s = 0; s < 6; s++) {
            if (soff[s] >= 0) {
                s_hr[soff[s]] = (goff[s] >= 0) ? pk(hp0[goff[s]], hp1[goff[s]]) : 0ull;
            }
        }
        __syncthreads();
#pragma unroll
        for (int s = 0; s < 5; s++) {
            if (hb_in[s] >= 0) {
                const u64* p = &s_hr[hb_in[s]];
                u64 v = f2_mul(g2_2, f2_add(p[0], p[4]));
                v = f2_fma(g1_2, f2_add(p[1], p[3]), v);
                v = f2_fma(g0_2, p[2], v);
                s_tmp[hb_out[s]] = f2_mul(v, hb_m[s]);
            }
        }
        __syncthreads();
#pragma unroll
        for (int s = 0; s < 5; s++) {
            if (vb_in[s] >= 0) {
                const u64* p = &s_tmp[vb_in[s]];
                u64 v = f2_mul(g2_2, f2_add(p[0], p[4 * B_BL_STRIDE]));
                v = f2_fma(g1_2, f2_add(p[B_BL_STRIDE], p[3 * B_BL_STRIDE]), v);
                v = f2_fma(g0_2, p[2 * B_BL_STRIDE], v);
                s_blr[vb_out[s]] = f2_mul(v, vb_m[s]);
            }
        }
        __syncthreads();

        const u64* brow = &s_blr[(2 * ty) * B_BL_STRIDE + 2 * tx];
        u64 r = 0ull;
#pragma unroll
        for (int kh = 0; kh < 3; kh++) {
#pragma unroll
            for (int kw = 0; kw < 3; kw++) {
                r = f2_fma(a2[kh * 3 + kw], brow[kh * B_BL_STRIDE + kw], r);
            }
        }
        float r0, r1; unpk(r, r0, r1);
        out_b[(long)(2 * pi) * FFFF + (long)y * FF + x] = r0;
        out_b[(long)(2 * pi + 1) * FFFF + (long)y * FF + x] = r1;
        __syncthreads();
    }
}

// ============================================================
// launch
// ============================================================
extern "C" void kernel_launch(void* const* d_in, const int* in_sizes, int n_in,
                              void* d_out, int out_size)
{
    const float* hr    = (const float*)d_in[0];
    const float* wk    = (const float*)d_in[1];
    const float* kbias = (const float*)d_in[2];
    const float* lbias = (const float*)d_in[3];
    const void*  mask  = (const void*)d_in[4];
    float* out = (float*)d_out;

    const double f1 = exp(-sqrt(2.0));
    const double f2 = exp(-4.0 * sqrt(2.0));
    const double s  = 1.0 + 2.0 * f1 + 2.0 * f2;
    const float g0 = (float)(1.0 / s);
    const float g1 = (float)(f1 / s);
    const float g2 = (float)(f2 / s);

    dim3 gA1(FF / ATW, FF / ATH, NB * SPLIT);      // (7, 14, 8)
    attn_A1<<<gA1, A_THREADS>>>(hr, wk, g0, g1, g2);

    attn_A2<<<(NB * FFFF + 255) / 256, 256>>>(kbias, lbias, mask);

    dim3 gB(FF / BTW, FF / BTH, NB * (NC / CG));   // (7, 7, 128)
    attn_B<<<gB, B_THREADS>>>(hr, out, g0, g1, g2);
}

// round 8
// speedup vs baseline: 1.2411x; 1.2411x over previous
#include <cuda_runtime.h>
#include <math.h>

// Problem constants
#define NB 4
#define NC 256
#define IH 224
#define IW 224
#define FF 112
#define FFFF (FF*FF)
#define HWSZ (IH*IW)
#define CHWSZ (NC*HWSZ)
#define SPLIT 4
#define CPS (NC/SPLIT)       // channels per split = 64

// ---------------- shared tiling (A1 and B): 16x16 out tile, 256 threads ----
#define TH 16
#define TW 16
#define NT 256
#define HRR 37
#define HRC 37
#define HRS 40
#define BLC 33
#define BLS 36
#define BLRR 33
#define NS_HR 6          // ceil(37*37/256)
#define NS_HB 5          // ceil(37*33/256)
#define NS_VB 5          // ceil(33*33/256)
#define CG 8             // kernel B channels per CTA

typedef unsigned long long u64;

// scratch: partial logits (4*4, 9, 112, 112) = 7.2 MB ; attn (4, 9, 112, 112) = 1.8 MB
__device__ float g_part[NB * SPLIT * 9 * FFFF];
__device__ float g_attn[NB * 9 * FFFF];

// ---------------- f32x2 packed helpers ----------------
__device__ __forceinline__ u64 pk(float lo, float hi) {
    u64 d; asm("mov.b64 %0,{%1,%2};" : "=l"(d) : "f"(lo), "f"(hi)); return d;
}
__device__ __forceinline__ void unpk(u64 v, float& lo, float& hi) {
    asm("mov.b64 {%0,%1},%2;" : "=f"(lo), "=f"(hi) : "l"(v));
}
__device__ __forceinline__ u64 f2_add(u64 a, u64 b) {
    u64 d; asm("add.rn.f32x2 %0,%1,%2;" : "=l"(d) : "l"(a), "l"(b)); return d;
}
__device__ __forceinline__ u64 f2_mul(u64 a, u64 b) {
    u64 d; asm("mul.rn.f32x2 %0,%1,%2;" : "=l"(d) : "l"(a), "l"(b)); return d;
}
__device__ __forceinline__ u64 f2_fma(u64 a, u64 b, u64 c) {
    u64 d; asm("fma.rn.f32x2 %0,%1,%2,%3;" : "=l"(d) : "l"(a), "l"(b), "l"(c)); return d;
}

// ---- mask dtype sniffing (JAX bool may arrive as int32 / float32 / uint8) ----
__device__ __forceinline__ int detect_mask_mode(const void* m) {
    const unsigned int* w = (const unsigned int*)m;
    bool all01 = true, allf = true;
#pragma unroll
    for (int i = 0; i < 32; i++) {
        unsigned int v = w[i];
        if (v > 1u) all01 = false;
        if (v != 0u && v != 0x3F800000u) allf = false;
    }
    return all01 ? 0 : (allf ? 1 : 2);
}
__device__ __forceinline__ bool mask_val(const void* m, int mode, long idx) {
    if (mode == 0) return ((const int*)m)[idx] != 0;
    if (mode == 1) return ((const float*)m)[idx] != 0.0f;
    return ((const unsigned char*)m)[idx] != 0;
}

// ---------------- compact slot state (register-budget optimized) ----------
// hblur: input offset = dst + 4*i  (HRS-BLS = 4); i packed 6 bits/slot.
// vblur: input offset == output offset (both i*BLS+j) -> single array.
// Edge zero-masks: one bit per slot; multiply by {0,1} replaced by select.
struct Slots {
    int goff[NS_HR], soff[NS_HR];
    int hb_dst[NS_HB];
    unsigned hb_i;       // 5 x 6-bit row index
    unsigned hb_msk;     // bit s: keep value (0 -> force exact 0, unfold left pad)
    int vb_off[NS_VB];
    unsigned vb_msk;     // bit s: keep value (0 -> force exact 0, unfold top pad)
};

__device__ __forceinline__ void make_slots(Slots& S, int tid, int tx0, int ty0) {
    const int R0 = 2 * ty0 - 3;
    const int C0 = 2 * tx0 - 3;
#pragma unroll
    for (int s = 0; s < NS_HR; s++) {
        int idx = tid + s * NT;
        if (idx < HRR * HRC) {
            int i = idx / HRC, j = idx % HRC;
            int gr = R0 + i, gc = C0 + j;
            S.soff[s] = i * HRS + j;
            S.goff[s] = (gr >= 0 && gr < IH && gc >= 0 && gc < IW) ? (gr * IW + gc) : -1;
        } else { S.soff[s] = -1; S.goff[s] = -1; }
    }
    S.hb_i = 0u; S.hb_msk = 0u;
#pragma unroll
    for (int s = 0; s < NS_HB; s++) {
        int idx = tid + s * NT;
        if (idx < HRR * BLC) {
            int i = idx / BLC, j = idx % BLC;
            S.hb_dst[s] = i * BLS + j;
            S.hb_i |= (unsigned)i << (6 * s);
            if ((2 * tx0 - 1 + j) >= 0) S.hb_msk |= 1u << s;
        } else S.hb_dst[s] = -1;
    }
    S.vb_msk = 0u;
#pragma unroll
    for (int s = 0; s < NS_VB; s++) {
        int idx = tid + s * NT;
        if (idx < BLRR * BLC) {
            int i = idx / BLC, j = idx % BLC;
            S.vb_off[s] = i * BLS + j;
            if ((2 * ty0 - 1 + i) >= 0) S.vb_msk |= 1u << s;
        } else S.vb_off[s] = -1;
    }
}

// ============================================================
// Kernel A1: blur -> 3x3 stride-2 conv, 9 out ch, partial over 64 channels
// grid (7, 7, NB*SPLIT=16), block 256 ; 2 channels/iter (f32x2), pipelined,
// 3 barriers/iter (trailing barrier proved redundant: s_hr last read before
// barrier B; conv touches only s_blr + double-buffered s_w).
// ============================================================
__global__ __launch_bounds__(NT, 3)
void attn_A1(const float* __restrict__ hr,
             const float* __restrict__ wk,     // (9,256,3,3)
             float g0, float g1, float g2)
{
    __shared__ __align__(16) u64 s_hr[HRR * HRS];
    __shared__ __align__(16) u64 s_tmp[HRR * BLS];
    __shared__ __align__(16) u64 s_blr[BLRR * BLS];
    __shared__ __align__(16) u64 s_w[2][9 * 12];   // double-buffered [tap][outk]

    const int z     = blockIdx.z;
    const int b     = z / SPLIT;
    const int cbase = (z % SPLIT) * CPS;
    const int tx0 = blockIdx.x * TW;
    const int ty0 = blockIdx.y * TH;
    const int tid = threadIdx.x;

    const u64 g0_2 = pk(g0, g0), g1_2 = pk(g1, g1), g2_2 = pk(g2, g2);

    Slots S;
    make_slots(S, tid, tx0, ty0);

    const int ty = tid / TW, tx = tid % TW;

    u64 acc[9];
#pragma unroll
    for (int k = 0; k < 9; k++) acc[k] = 0ull;

    const float* hr_b = hr + (long)b * CHWSZ + (long)cbase * HWSZ;
    const int wk_k = tid / 9, wk_t = tid % 9;
    const bool wthr = (tid < 81);

    // -------- prologue prefetch: iteration 0 --------
    float r0[NS_HR], r1[NS_HR];
    float wa = 0.0f, wb = 0.0f;
    {
        const float* hp0 = hr_b;
        const float* hp1 = hp0 + HWSZ;
#pragma unroll
        for (int s = 0; s < NS_HR; s++) {
            r0[s] = (S.goff[s] >= 0) ? hp0[S.goff[s]] : 0.0f;
            r1[s] = (S.goff[s] >= 0) ? hp1[S.goff[s]] : 0.0f;
        }
        if (wthr) {
            const float* wp = &wk[(wk_k * NC + cbase) * 9 + wk_t];
            wa = wp[0]; wb = wp[9];
        }
    }

#pragma unroll 1
    for (int ci = 0; ci < CPS / 2; ci++) {
        const int buf = ci & 1;
        // store staged registers into smem
#pragma unroll
        for (int s = 0; s < NS_HR; s++) {
            if (S.soff[s] >= 0) s_hr[S.soff[s]] = pk(r0[s], r1[s]);
        }
        if (wthr) s_w[buf][wk_t * 12 + wk_k] = pk(wa, wb);

        // prefetch next iteration (overlaps everything below)
        if (ci + 1 < CPS / 2) {
            const float* hp0 = hr_b + (2 * ci + 2) * HWSZ;
            const float* hp1 = hp0 + HWSZ;
#pragma unroll
            for (int s = 0; s < NS_HR; s++) {
                r0[s] = (S.goff[s] >= 0) ? hp0[S.goff[s]] : 0.0f;
                r1[s] = (S.goff[s] >= 0) ? hp1[S.goff[s]] : 0.0f;
            }
            if (wthr) {
                const float* wp = &wk[(wk_k * NC + cbase + 2 * ci + 2) * 9 + wk_t];
                wa = wp[0]; wb = wp[9];
            }
        }
        __syncthreads();   // A: s_hr / s_w[buf] ready

        // horizontal 5-tap blur
#pragma unroll
        for (int s = 0; s < NS_HB; s++) {
            const int d = S.hb_dst[s];
            if (d >= 0) {
                const int i = (S.hb_i >> (6 * s)) & 63;
                const u64* p = &s_hr[d + 4 * i];
                u64 v = f2_mul(g2_2, f2_add(p[0], p[4]));
                v = f2_fma(g1_2, f2_add(p[1], p[3]), v);
                v = f2_fma(g0_2, p[2], v);
                s_tmp[d] = ((S.hb_msk >> s) & 1u) ? v : 0ull;
            }
        }
        __syncthreads();   // B: s_tmp ready (s_hr free for next-iter stores)

        // vertical 5-tap blur
#pragma unroll
        for (int s = 0; s < NS_VB; s++) {
            const int o = S.vb_off[s];
            if (o >= 0) {
                const u64* p = &s_tmp[o];
                u64 v = f2_mul(g2_2, f2_add(p[0], p[4 * BLS]));
                v = f2_fma(g1_2, f2_add(p[BLS], p[3 * BLS]), v);
                v = f2_fma(g0_2, p[2 * BLS], v);
                s_blr[o] = ((S.vb_msk >> s) & 1u) ? v : 0ull;
            }
        }
        __syncthreads();   // C: s_blr ready

        // 3x3 stride-2 conv -> 9 out channels (packed 2 input channels).
        // No trailing barrier (proof in header comment).
        const u64* brow = &s_blr[(2 * ty) * BLS + 2 * tx];
        const u64* wrow = s_w[buf];
#pragma unroll
        for (int kh = 0; kh < 3; kh++) {
#pragma unroll
            for (int kw = 0; kw < 3; kw++) {
                const int t = kh * 3 + kw;
                const ulonglong2* wp = (const ulonglong2*)&wrow[t * 12];
                const u64 v = brow[kh * BLS + kw];
                const ulonglong2 w01 = wp[0];
                const ulonglong2 w23 = wp[1];
                const ulonglong2 w45 = wp[2];
                const ulonglong2 w67 = wp[3];
                const u64 w8 = wrow[t * 12 + 8];
                acc[0] = f2_fma(v, w01.x, acc[0]);
                acc[1] = f2_fma(v, w01.y, acc[1]);
                acc[2] = f2_fma(v, w23.x, acc[2]);
                acc[3] = f2_fma(v, w23.y, acc[3]);
                acc[4] = f2_fma(v, w45.x, acc[4]);
                acc[5] = f2_fma(v, w45.y, acc[5]);
                acc[6] = f2_fma(v, w67.x, acc[6]);
                acc[7] = f2_fma(v, w67.y, acc[7]);
                acc[8] = f2_fma(v, w8,    acc[8]);
            }
        }
    }

    const int y = ty0 + ty, x = tx0 + tx;
    const long pbase = ((long)z * 9) * FFFF + (long)y * FF + x;
#pragma unroll
    for (int k = 0; k < 9; k++) {
        float lo, hi; unpk(acc[k], lo, hi);
        g_part[pbase + (long)k * FFFF] = lo + hi;
    }
}

// ============================================================
// Kernel A2: combine 4 partials + kbias, mask, lbias, softmax -> g_attn
// ============================================================
__global__ __launch_bounds__(256)
void attn_A2(const float* __restrict__ kbias,
             const float* __restrict__ lbias,
             const void*  __restrict__ mask)
{
    const int idx = blockIdx.x * 256 + threadIdx.x;
    if (idx >= NB * FFFF) return;
    const int b = idx / FFFF;
    const int p = idx % FFFF;
    const int mode = detect_mask_mode(mask);

    long pp[SPLIT];
#pragma unroll
    for (int s = 0; s < SPLIT; s++)
        pp[s] = ((long)(b * SPLIT + s) * 9) * FFFF + p;
    const long mbase = ((long)b * 9) * FFFF + p;

    float lg[9];
    float mx = -1e30f;
#pragma unroll
    for (int k = 0; k < 9; k++) {
        const long ko = (long)k * FFFF;
        float l = (g_part[pp[0] + ko] + g_part[pp[1] + ko])
                + (g_part[pp[2] + ko] + g_part[pp[3] + ko]) + kbias[k];
        bool mk = mask_val(mask, mode, mbase + ko);
        l = (mk ? l : 0.0f) + lbias[k];
        lg[k] = l;
        mx = fmaxf(mx, l);
    }
    float sum = 0.0f;
#pragma unroll
    for (int k = 0; k < 9; k++) { lg[k] = expf(lg[k] - mx); sum += lg[k]; }
    const float inv = 1.0f / sum;
#pragma unroll
    for (int k = 0; k < 9; k++) g_attn[mbase + (long)k * FFFF] = lg[k] * inv;
}

// ============================================================
// Kernel B: out[b,c,y,x] = sum_k blurred[b,c,2y-1+kh,2x-1+kw] * attn[b,k,y,x]
// grid (7, 7, 128), block 256 ; CG=8 channels, 2/iter packed, pipelined,
// 3 barriers/iter (same redundancy proof as A1).
// ============================================================
__global__ __launch_bounds__(NT, 3)
void attn_B(const float* __restrict__ hr,
            float* __restrict__ out,
            float g0, float g1, float g2)
{
    __shared__ __align__(16) u64 s_hr[HRR * HRS];
    __shared__ __align__(16) u64 s_tmp[HRR * BLS];
    __shared__ __align__(16) u64 s_blr[BLRR * BLS];

    const int z  = blockIdx.z;
    const int b  = z / (NC / CG);
    const int cg = z % (NC / CG);
    const int tx0 = blockIdx.x * TW;
    const int ty0 = blockIdx.y * TH;
    const int tid = threadIdx.x;
    const int ty = tid / TW, tx = tid % TW;
    const int y = ty0 + ty, x = tx0 + tx;

    const u64 g0_2 = pk(g0, g0), g1_2 = pk(g1, g1), g2_2 = pk(g2, g2);

    // attn broadcast-packed (same weight applied to both packed channels)
    u64 a2[9];
    {
        const long abase = ((long)b * 9) * FFFF + (long)y * FF + x;
#pragma unroll
        for (int k = 0; k < 9; k++) {
            float a = g_attn[abase + (long)k * FFFF];
            a2[k] = pk(a, a);
        }
    }

    Slots S;
    make_slots(S, tid, tx0, ty0);

    const float* hr_b = hr + (long)b * CHWSZ + (long)cg * CG * HWSZ;
    float* out_b = out + ((long)b * NC + (long)cg * CG) * FFFF;

    // prologue prefetch
    float r0[NS_HR], r1[NS_HR];
    {
        const float* hp0 = hr_b;
        const float* hp1 = hp0 + HWSZ;
#pragma unroll
        for (int s = 0; s < NS_HR; s++) {
            r0[s] = (S.goff[s] >= 0) ? hp0[S.goff[s]] : 0.0f;
            r1[s] = (S.goff[s] >= 0) ? hp1[S.goff[s]] : 0.0f;
        }
    }

#pragma unroll 1
    for (int pi = 0; pi < CG / 2; pi++) {
#pragma unroll
        for (int s = 0; s < NS_HR; s++) {
            if (S.soff[s] >= 0) s_hr[S.soff[s]] = pk(r0[s], r1[s]);
        }
        if (pi + 1 < CG / 2) {
            const float* hp0 = hr_b + (2 * pi + 2) * HWSZ;
            const float* hp1 = hp0 + HWSZ;
#pragma unroll
            for (int s = 0; s < NS_HR; s++) {
                r0[s] = (S.goff[s] >= 0) ? hp0[S.goff[s]] : 0.0f;
                r1[s] = (S.goff[s] >= 0) ? hp1[S.goff[s]] : 0.0f;
            }
        }
        __syncthreads();   // A
#pragma unroll
        for (int s = 0; s < NS_HB; s++) {
            const int d = S.hb_dst[s];
            if (d >= 0) {
                const int i = (S.hb_i >> (6 * s)) & 63;
                const u64* p = &s_hr[d + 4 * i];
                u64 v = f2_mul(g2_2, f2_add(p[0], p[4]));
                v = f2_fma(g1_2, f2_add(p[1], p[3]), v);
                v = f2_fma(g0_2, p[2], v);
                s_tmp[d] = ((S.hb_msk >> s) & 1u) ? v : 0ull;
            }
        }
        __syncthreads();   // B
#pragma unroll
        for (int s = 0; s < NS_VB; s++) {
            const int o = S.vb_off[s];
            if (o >= 0) {
                const u64* p = &s_tmp[o];
                u64 v = f2_mul(g2_2, f2_add(p[0], p[4 * BLS]));
                v = f2_fma(g1_2, f2_add(p[BLS], p[3 * BLS]), v);
                v = f2_fma(g0_2, p[2 * BLS], v);
                s_blr[o] = ((S.vb_msk >> s) & 1u) ? v : 0ull;
            }
        }
        __syncthreads();   // C

        const u64* brow = &s_blr[(2 * ty) * BLS + 2 * tx];
        u64 r = 0ull;
#pragma unroll
        for (int kh = 0; kh < 3; kh++) {
#pragma unroll
            for (int kw = 0; kw < 3; kw++) {
                r = f2_fma(a2[kh * 3 + kw], brow[kh * BLS + kw], r);
            }
        }
        float rl, rh; unpk(r, rl, rh);
        out_b[(long)(2 * pi) * FFFF + (long)y * FF + x] = rl;
        out_b[(long)(2 * pi + 1) * FFFF + (long)y * FF + x] = rh;
        // no trailing barrier (same proof as A1)
    }
}

// ============================================================
// launch
// ============================================================
extern "C" void kernel_launch(void* const* d_in, const int* in_sizes, int n_in,
                              void* d_out, int out_size)
{
    const float* hr    = (const float*)d_in[0];
    const float* wk    = (const float*)d_in[1];
    const float* kbias = (const float*)d_in[2];
    const float* lbias = (const float*)d_in[3];
    const void*  mask  = (const void*)d_in[4];
    float* out = (float*)d_out;

    const double f1 = exp(-sqrt(2.0));
    const double f2 = exp(-4.0 * sqrt(2.0));
    const double s  = 1.0 + 2.0 * f1 + 2.0 * f2;
    const float g0 = (float)(1.0 / s);
    const float g1 = (float)(f1 / s);
    const float g2 = (float)(f2 / s);

    dim3 gA1(FF / TW, FF / TH, NB * SPLIT);        // (7, 7, 16)
    attn_A1<<<gA1, NT>>>(hr, wk, g0, g1, g2);

    attn_A2<<<(NB * FFFF + 255) / 256, 256>>>(kbias, lbias, mask);

    dim3 gB(FF / TW, FF / TH, NB * (NC / CG));     // (7, 7, 128)
    attn_B<<<gB, NT>>>(hr, out, g0, g1, g2);
}